// round 1
// baseline (speedup 1.0000x reference)
#include <cuda_runtime.h>
#include <math.h>

// A[b,i,j] = softmax_i(s_i + s_j + bias) = exp(s_i)/sum_i' exp(s_i')
// (s_j and bias cancel in softmax over axis=1). Output row (b,i,:) is a
// constant value p[b,i] broadcast N wide -> the kernel is a 268MB fill.

#define MAX_BN 16384  // B*N for B=4, N=4096

__device__ float g_s[MAX_BN];
__device__ float g_p[MAX_BN];

// ---- kernel 1: s[row] = dot(h[row,:], w), one warp per row ----
__global__ void dot_rows_kernel(const float* __restrict__ h,
                                const float* __restrict__ w,
                                float* __restrict__ s,
                                int BN, int D) {
    int row  = blockIdx.x * (blockDim.x >> 5) + (threadIdx.x >> 5);
    int lane = threadIdx.x & 31;
    if (row >= BN) return;

    const float4* hr = reinterpret_cast<const float4*>(h + (size_t)row * D);
    const float4* wv = reinterpret_cast<const float4*>(w);
    int D4 = D >> 2;

    float acc = 0.0f;
    for (int c = lane; c < D4; c += 32) {
        float4 a = hr[c];
        float4 b = wv[c];
        acc += a.x * b.x + a.y * b.y + a.z * b.z + a.w * b.w;
    }
    #pragma unroll
    for (int o = 16; o; o >>= 1)
        acc += __shfl_xor_sync(0xFFFFFFFFu, acc, o);
    if (lane == 0) s[row] = acc;
}

// ---- kernel 2: per-batch softmax over N values (one block per batch) ----
__global__ void softmax_kernel(const float* __restrict__ s,
                               float* __restrict__ p,
                               int N) {
    __shared__ float red[32];
    const float* sb = s + (size_t)blockIdx.x * N;
    float*       pb = p + (size_t)blockIdx.x * N;
    int tid  = threadIdx.x;
    int nthr = blockDim.x;
    int lane = tid & 31;
    int wid  = tid >> 5;
    int nw   = nthr >> 5;

    // local max
    float m = -INFINITY;
    for (int i = tid; i < N; i += nthr) m = fmaxf(m, sb[i]);
    #pragma unroll
    for (int o = 16; o; o >>= 1) m = fmaxf(m, __shfl_xor_sync(0xFFFFFFFFu, m, o));
    if (lane == 0) red[wid] = m;
    __syncthreads();
    if (wid == 0) {
        float v = (lane < nw) ? red[lane] : -INFINITY;
        #pragma unroll
        for (int o = 16; o; o >>= 1) v = fmaxf(v, __shfl_xor_sync(0xFFFFFFFFu, v, o));
        if (lane == 0) red[0] = v;
    }
    __syncthreads();
    m = red[0];
    __syncthreads();

    // local sum of exp
    float sum = 0.0f;
    for (int i = tid; i < N; i += nthr) sum += __expf(sb[i] - m);
    #pragma unroll
    for (int o = 16; o; o >>= 1) sum += __shfl_xor_sync(0xFFFFFFFFu, sum, o);
    if (lane == 0) red[wid] = sum;
    __syncthreads();
    if (wid == 0) {
        float v = (lane < nw) ? red[lane] : 0.0f;
        #pragma unroll
        for (int o = 16; o; o >>= 1) v += __shfl_xor_sync(0xFFFFFFFFu, v, o);
        if (lane == 0) red[0] = v;
    }
    __syncthreads();
    float inv = 1.0f / red[0];

    for (int i = tid; i < N; i += nthr)
        pb[i] = __expf(sb[i] - m) * inv;
}

// ---- kernel 3: broadcast-fill, one block per output row ----
__global__ void fill_kernel(const float* __restrict__ p,
                            float4* __restrict__ out,
                            int N4) {
    size_t row = blockIdx.x;
    float v = __ldg(&p[row]);
    float4 v4 = make_float4(v, v, v, v);
    float4* o = out + row * (size_t)N4;
    for (int c = threadIdx.x; c < N4; c += blockDim.x)
        __stcs(&o[c], v4);
}

extern "C" void kernel_launch(void* const* d_in, const int* in_sizes, int n_in,
                              void* d_out, int out_size) {
    const float* h = (const float*)d_in[0];
    const float* w = (const float*)d_in[1];
    // d_in[2] (bias) cancels in softmax over axis=1 -> unused.

    int D  = in_sizes[1];                 // 256
    int BN = in_sizes[0] / D;             // B*N = 16384
    // out_size = B*N*N -> N = out_size / BN
    int N  = (int)((long long)out_size / BN);
    float* out = (float*)d_out;

    float* s = nullptr;
    float* p = nullptr;
    cudaGetSymbolAddress((void**)&s, g_s);
    cudaGetSymbolAddress((void**)&p, g_p);

    // 1. per-row dot products: 4 warps/block
    {
        int warps_per_block = 4;
        int blocks = (BN + warps_per_block - 1) / warps_per_block;
        dot_rows_kernel<<<blocks, warps_per_block * 32>>>(h, w, s, BN, D);
    }

    // 2. per-batch softmax
    {
        int B = BN / N;
        softmax_kernel<<<B, 1024>>>(s, p, N);
    }

    // 3. broadcast fill (HBM-write bound)
    {
        fill_kernel<<<BN, 256>>>(p, (float4*)out, N >> 2);
    }
}